// round 1
// baseline (speedup 1.0000x reference)
#include <cuda_runtime.h>

// Embedding_6940667150787: out[i][d] = wordlist[idx[i]][d] + PE(i, d)
// PE(i, 2j)   = sin(i / 10000^(j/256))   j in [0, 255)
// PE(i, 2j+1) = cos(i / 10000^(j/256))
// cols 510, 511: PE = 0 (emb only)

#define NROWS 131072
#define DEPTH 512
#define NPAIR 255

// Correctly-rounded fp32 table of p_j = 10000^(j/256), computed in double once
// per launch by a tiny setup kernel (graph-capturable; no allocations).
__device__ float g_P[256];

__global__ void setup_P_kernel() {
    int j = threadIdx.x;
    if (j < 256) {
        // ln(10000) in double
        double e = (double)j * (1.0 / 256.0);
        double p = exp(e * 9.210340371976184);
        g_P[j] = (j < NPAIR) ? (float)p : 1.0f;  // j=255 unused; avoid div-by-0 paths
    }
}

__global__ __launch_bounds__(256) void emb_pe_kernel(
    const int* __restrict__ idx,
    const float* __restrict__ wl,
    float* __restrict__ out)
{
    const int t = threadIdx.x;

    // Per-thread frequency divisor (held in register across the row loop)
    const float p = g_P[t];

    // Range-reduction constants: pi/2 = C1 + C2 (fp32 split), 2/pi
    const float TWO_OVER_PI = 0.63661977236758134f;
    const float C1 = 1.57079637e+00f;    // fl(pi/2)
    const float C2 = -4.37113883e-08f;   // fl(pi/2 - C1)

    const bool has_pe = (t < NPAIR);

    for (int i = blockIdx.x; i < NROWS; i += gridDim.x) {
        const int tok = __ldg(&idx[i]);   // uniform within block (broadcast)

        // gather embedding pair (wordlist is L2-resident: 198*512*4 = 405 KB)
        float2 w = *reinterpret_cast<const float2*>(wl + (size_t)tok * DEPTH + 2 * t);

        float2 o;
        if (has_pe) {
            // angle exactly as the reference computes it in fp32:
            // a = fl( fl(i) / p )  with IEEE-correct division (nvcc default div.rn)
            const float fi = (float)i;           // exact, i < 2^24
            const float a  = fi / p;

            // accurate sin/cos of the fp32 angle:
            // k = rint(a * 2/pi); r = a - k*pi/2 via 2-term FMA Cody-Waite
            // (k <= 83443 < 2^17 -> residual error < 1e-7)
            const float kf = rintf(a * TWO_OVER_PI);
            const int   q  = ((int)kf) & 3;
            const float r  = fmaf(-kf, C2, fmaf(-kf, C1, a));

            float s, c;
            asm("sin.approx.f32 %0, %1;" : "=f"(s) : "f"(r));
            asm("cos.approx.f32 %0, %1;" : "=f"(c) : "f"(r));

            // quadrant fixup:
            // sin(a) = { s, c, -s, -c }[q]   cos(a) = { c, -s, -c, s }[q]
            float sa = (q & 1) ? c : s;
            float ca = (q & 1) ? s : c;
            if (q & 2)       sa = -sa;
            if ((q + 1) & 2) ca = -ca;

            o.x = w.x + sa;
            o.y = w.y + ca;
        } else {
            // t == 255: cols 510, 511 have zero PE
            o = w;
        }

        *reinterpret_cast<float2*>(out + (size_t)i * DEPTH + 2 * t) = o;
    }
}

extern "C" void kernel_launch(void* const* d_in, const int* in_sizes, int n_in,
                              void* d_out, int out_size) {
    const int*   idx = (const int*)d_in[0];
    const float* wl  = (const float*)d_in[1];
    float*       out = (float*)d_out;

    (void)in_sizes; (void)n_in; (void)out_size;

    setup_P_kernel<<<1, 256>>>();
    emb_pe_kernel<<<4096, 256>>>(idx, wl, out);
}

// round 2
// speedup vs baseline: 1.9105x; 1.9105x over previous
#include <cuda_runtime.h>

// Embedding_6940667150787: out[i][d] = wordlist[idx[i]][d] + PE(i, d)
// PE(i, 2j)   = sin(i / 10000^(j/256))   j in [0, 255)
// PE(i, 2j+1) = cos(i / 10000^(j/256))
// cols 510, 511: PE = 0 (emb only)

#define NROWS 131072
#define DEPTH 512
#define NPAIR 255
#define GRID  4096
#define ROWS_PER_BLOCK (NROWS / GRID)   // 32

// Correctly-rounded fp32 tables: p_j = 10000^(j/256) and fl(1/p_j),
// computed in double once per launch (graph-capturable, no allocations).
__device__ float g_P[256];
__device__ float g_RP[256];

__global__ void setup_P_kernel() {
    int j = threadIdx.x;
    if (j < 256) {
        double p = exp((double)j * (9.210340371976184 / 256.0)); // ln(10000)/256
        float pf = (j < NPAIR) ? (float)p : 1.0f;                // j=255 unused
        g_P[j]  = pf;
        g_RP[j] = (float)(1.0 / (double)pf);                     // correctly rounded 1/pf
    }
}

// sin/cos of a = fl(fi / p) where the quotient is correctly rounded
// (Markstein 3-FMA division with correctly-rounded reciprocal), then
// FMA Cody-Waite reduction (k <= 83444 < 2^17 -> residual < 1e-7) + MUFU.
__device__ __forceinline__ void sincos_ref(float fi, float p, float rp,
                                           float& sa, float& ca) {
    const float TWO_OVER_PI = 0.63661977236758134f;
    const float C1 = 1.57079637e+00f;    // fl(pi/2)
    const float C2 = -4.37113883e-08f;   // fl(pi/2 - C1)

    float a0 = fi * rp;
    float e  = fmaf(-p, a0, fi);
    float a  = fmaf(e, rp, a0);          // == div.rn(fi, p)

    int   k  = __float2int_rn(a * TWO_OVER_PI);
    float kf = (float)k;
    float r  = fmaf(-kf, C1, a);
    r        = fmaf(-kf, C2, r);

    float s, c;
    asm("sin.approx.f32 %0, %1;" : "=f"(s) : "f"(r));
    asm("cos.approx.f32 %0, %1;" : "=f"(c) : "f"(r));

    // quadrant fixup via swap + sign-bit XOR
    float ss = (k & 1) ? c : s;
    float cc = (k & 1) ? s : c;
    sa = __int_as_float(__float_as_int(ss) ^ ((k & 2) << 30));
    ca = __int_as_float(__float_as_int(cc) ^ (((k + 1) & 2) << 30));
}

__global__ __launch_bounds__(128) void emb_pe_kernel(
    const int* __restrict__ idx,
    const float* __restrict__ wl,
    float* __restrict__ out)
{
    const int t  = threadIdx.x;          // 128 threads: thread t owns cols 4t..4t+3
    const int j0 = 2 * t;
    const int j1 = 2 * t + 1;

    const float p0 = g_P[j0], rp0 = g_RP[j0];
    const float p1 = g_P[j1], rp1 = g_RP[j1];
    const bool pe1 = (j1 < NPAIR);       // false only for t == 127 (cols 510,511)

    const int base = blockIdx.x * ROWS_PER_BLOCK;
    const float4* __restrict__ wl4  = reinterpret_cast<const float4*>(wl);
    float4* __restrict__       out4 = reinterpret_cast<float4*>(out);

    #pragma unroll 1
    for (int k = 0; k < ROWS_PER_BLOCK; k += 2) {
        const int i0 = base + k;
        const int i1 = i0 + 1;

        // two independent load chains in flight
        const int tok0 = __ldg(idx + i0);
        const int tok1 = __ldg(idx + i1);
        float4 w0 = __ldg(wl4 + (size_t)tok0 * (DEPTH / 4) + t);
        float4 w1 = __ldg(wl4 + (size_t)tok1 * (DEPTH / 4) + t);

        float s, c;
        const float f0 = (float)i0;      // exact, i < 2^24
        const float f1 = (float)i1;

        sincos_ref(f0, p0, rp0, s, c); w0.x += s; w0.y += c;
        if (pe1) { sincos_ref(f0, p1, rp1, s, c); w0.z += s; w0.w += c; }

        sincos_ref(f1, p0, rp0, s, c); w1.x += s; w1.y += c;
        if (pe1) { sincos_ref(f1, p1, rp1, s, c); w1.z += s; w1.w += c; }

        // streaming stores: output is never re-read; keep L2 for the wordlist
        __stcs(out4 + (size_t)i0 * (DEPTH / 4) + t, w0);
        __stcs(out4 + (size_t)i1 * (DEPTH / 4) + t, w1);
    }
}

extern "C" void kernel_launch(void* const* d_in, const int* in_sizes, int n_in,
                              void* d_out, int out_size) {
    const int*   idx = (const int*)d_in[0];
    const float* wl  = (const float*)d_in[1];
    float*       out = (float*)d_out;

    (void)in_sizes; (void)n_in; (void)out_size;

    setup_P_kernel<<<1, 256>>>();
    emb_pe_kernel<<<GRID, 128>>>(idx, wl, out);
}

// round 3
// speedup vs baseline: 1.9118x; 1.0007x over previous
#include <cuda_runtime.h>

// Embedding_6940667150787: out[i][d] = wordlist[idx[i]][d] + PE(i, d)
// PE(i, 2j)   = sin(i / 10000^(j/256))   j in [0, 255)
// PE(i, 2j+1) = cos(i / 10000^(j/256))
// cols 510, 511: PE = 0 (emb only)

#define NROWS 131072
#define DEPTH 512
#define NPAIR 255
#define GRID  4096
#define ROWS_PER_BLOCK (NROWS / GRID)   // 32

// Correctly-rounded fp32 tables: p_j = 10000^(j/256) and fl(1/p_j),
// computed in double once per launch (graph-capturable, no allocations).
__device__ float g_P[256];
__device__ float g_RP[256];

__global__ void setup_P_kernel() {
    int j = threadIdx.x;
    if (j < 256) {
        double p = exp((double)j * (9.210340371976184 / 256.0)); // ln(10000)/256
        float pf = (j < NPAIR) ? (float)p : 1.0f;                // j=255 unused
        g_P[j]  = pf;
        g_RP[j] = (float)(1.0 / (double)pf);                     // correctly rounded 1/pf
    }
}

// sin/cos of a = fl(fi / p), quotient correctly rounded (Markstein 3-FMA with
// correctly-rounded reciprocal), FMA Cody-Waite reduction (k <= 83444 < 2^22,
// residual < 1e-7), MUFU sin/cos, quadrant via magic-number mantissa bits.
__device__ __forceinline__ void sincos_ref(float fi, float p, float rp,
                                           float& sa, float& ca) {
    const float TWO_OVER_PI = 0.63661977236758134f;
    const float C1    = 1.57079637e+00f;    // fl(pi/2)
    const float C2    = -4.37113883e-08f;   // fl(pi/2 - C1)
    const float MAGIC = 12582912.0f;        // 1.5 * 2^23

    float a0 = fi * rp;
    float e  = fmaf(-p, a0, fi);
    float a  = fmaf(e, rp, a0);             // == div.rn(fi, p)

    // round-to-nearest via magic add: kf float + k int in one FMA (no cvts)
    float m  = fmaf(a, TWO_OVER_PI, MAGIC); // mantissa LSBs hold k (a >= 0)
    int   b  = __float_as_int(m);
    float kf = m - MAGIC;

    float r  = fmaf(-kf, C1, a);
    r        = fmaf(-kf, C2, r);

    float s, c;
    asm("sin.approx.f32 %0, %1;" : "=f"(s) : "f"(r));
    asm("cos.approx.f32 %0, %1;" : "=f"(c) : "f"(r));

    // quadrant fixup: swap when k odd, sign via bit XOR
    float ss = (b & 1) ? c : s;
    float cc = (b & 1) ? s : c;
    sa = __int_as_float(__float_as_int(ss) ^ ((b & 2) << 30));
    ca = __int_as_float(__float_as_int(cc) ^ (((b + 1) & 2) << 30));
}

__global__ __launch_bounds__(128) void emb_pe_kernel(
    const int* __restrict__ idx,
    const float* __restrict__ wl,
    float* __restrict__ out)
{
    const int t  = threadIdx.x;          // thread t owns cols 4t..4t+3
    const int j0 = 2 * t;
    const int j1 = 2 * t + 1;

    const float p0 = g_P[j0], rp0 = g_RP[j0];
    const float p1 = g_P[j1], rp1 = g_RP[j1];
    const bool pe1 = (j1 < NPAIR);       // false only for t == 127 (cols 510,511)

    const int base = blockIdx.x * ROWS_PER_BLOCK;
    const float4* __restrict__ wl4  = reinterpret_cast<const float4*>(wl);
    float4* __restrict__       out4 = reinterpret_cast<float4*>(out);

    float fi = (float)base;              // exact, base < 2^24

    #pragma unroll 1
    for (int k = 0; k < ROWS_PER_BLOCK; k += 4) {
        const int i = base + k;

        // 4 independent gather chains in flight
        int tok[4];
        #pragma unroll
        for (int u = 0; u < 4; u++) tok[u] = __ldg(idx + i + u);

        float4 w[4];
        #pragma unroll
        for (int u = 0; u < 4; u++)
            w[u] = __ldg(wl4 + (size_t)tok[u] * (DEPTH / 4) + t);

        #pragma unroll
        for (int u = 0; u < 4; u++) {
            const float f = fi + (float)u;   // exact small-int add
            float s, c;
            sincos_ref(f, p0, rp0, s, c); w[u].x += s; w[u].y += c;
            if (pe1) { sincos_ref(f, p1, rp1, s, c); w[u].z += s; w[u].w += c; }
        }

        // streaming stores: output never re-read; keep L2 for the wordlist
        #pragma unroll
        for (int u = 0; u < 4; u++)
            __stcs(out4 + (size_t)(i + u) * (DEPTH / 4) + t, w[u]);

        fi += 4.0f;
    }
}

extern "C" void kernel_launch(void* const* d_in, const int* in_sizes, int n_in,
                              void* d_out, int out_size) {
    const int*   idx = (const int*)d_in[0];
    const float* wl  = (const float*)d_in[1];
    float*       out = (float*)d_out;

    (void)in_sizes; (void)n_in; (void)out_size;

    setup_P_kernel<<<1, 256>>>();
    emb_pe_kernel<<<GRID, 128>>>(idx, wl, out);
}